// round 14
// baseline (speedup 1.0000x reference)
#include <cuda_runtime.h>

// Problem constants (fixed by the reference module)
#define N_  16
#define D_  3
#define H_  160
#define W_  160
#define M_  8
#define K_  10
#define P_  15
#define PM_ 7               // (P-1)/2
#define OH_ (H_ - P_ + 1)   // 146
#define OW_ (W_ - P_ + 1)   // 146
#define MK_ (M_ * K_)       // 80
#define PLANE_ (OH_ * OW_)  // 21316

// Block = (n, k, rg). All 8 m for a given k sample the same (n, channels[k])
// plane. Plane rows staged as PAIRS: splane2[r][c] = (v[c], v[c+1]) so each
// bilinear tap-pair is ONE LDS.64 instead of two LDS.32.
// HTILE=12, RG=13 -> 2080 blocks = 2.007 waves at 7 blocks/SM (smem-capped).
// 5 column bands of 32 (last clamped to x0=114); overlaps write identical
// values (deterministic).
#define HTILE_ 12
#define RG_    13
#define SROWS_ 25                      // rows 0..24 needed (sy<=12, r<=12)
#define SPAIRS_ (SROWS_ * W_)          // 4000 float2 = 32000 B
#define NBLOCKS_ (N_ * K_ * RG_)       // 2080

__global__ __launch_bounds__(256, 7)
void fern_bits_kernel(
    const float* __restrict__ T,
    const float* __restrict__ dx1, const float* __restrict__ dx2,
    const float* __restrict__ dy1, const float* __restrict__ dy2,
    const float* __restrict__ th,  const float* __restrict__ amb,
    const int*   __restrict__ channels,
    float* __restrict__ out)
{
    __shared__ float2 splane2[SPAIRS_];

    // ---- block decode: bid = (n*K + k)*RG + rg ----
    const int bid = blockIdx.x;
    const int rg  = bid % RG_;
    const int nk  = bid / RG_;
    const int k   = nk % K_;
    const int n   = nk / K_;
    const int ch  = channels[k];

    const int y0 = min(rg * HTILE_, OH_ - HTILE_);   // 0,12,...,132,134
    // staged plane rows [y0, y0+24]; max = 134+24 = 158 < 160. OK.

    // ---- cooperative pair staging ----
    const float* __restrict__ img = T + ((size_t)(n * D_ + ch)) * (H_ * W_);
    {
        const float* imgrow = img + y0 * W_;
        const float4* __restrict__ g4 = (const float4*)imgrow;
        for (int i = threadIdx.x; i < SPAIRS_ / 4; i += 256) {
            const float4 v = g4[i];
            // next element; clamp keeps the (unread) last pair in-bounds
            const float vn = imgrow[min(4 * i + 4, SPAIRS_ - 1)];
            splane2[4 * i + 0] = make_float2(v.x, v.y);
            splane2[4 * i + 1] = make_float2(v.y, v.z);
            splane2[4 * i + 2] = make_float2(v.z, v.w);
            splane2[4 * i + 3] = make_float2(v.w, vn);
        }
    }
    __syncthreads();

    // ---- per-warp: one m value ----
    const int m    = threadIdx.x >> 5;
    const int lane = threadIdx.x & 31;
    const int mk   = m * K_ + k;
    const int nmk  = n * MK_ + mk;

    // per-(m,k) parameters (uniform per warp, broadcast loads)
    const float a1x = dx1[mk], a2x = dx2[mk];
    const float a1y = dy1[mk], a2y = dy2[mk];
    const float fl1x = floorf(a1x), fl2x = floorf(a2x);
    const float fl1y = floorf(a1y), fl2y = floorf(a2y);
    const float f1x = a1x - fl1x, f2x = a2x - fl2x;
    const float f1y = a1y - fl1y, f2y = a2y - fl2y;
    const float g1x = 1.0f - f1x, g2x = 1.0f - f2x;
    const float g1y  = 1.0f - f1y;
    const float ng2y = -(1.0f - f2y), nf2y = -f2y;
    const int sx1 = PM_ + (int)fl1x, sx2 = PM_ + (int)fl2x;
    const int sy1 = PM_ + (int)fl1y, sy2 = PM_ + (int)fl2y;

    const float thv = th[mk];
    const float pos = amb[(m * 2 + 0) * K_ + k];
    const float neg = amb[(m * 2 + 1) * K_ + k];
    const float inv = 1.0f / (pos - neg + 1e-29f);
    const float c   = -(thv + neg) * inv;   // v = sat(temp*inv + c)

    // ---- sweep 5 column bands; 12 rolling rows, fully unrolled ----
    #pragma unroll 1
    for (int cb = 0; cb < 5; cb++) {
        const int x0 = min(cb * 32, OW_ - 32);   // 0,32,64,96,114
        const int x  = x0 + lane;

        // pair-array tap bases: row sy+r <= 24 < 25; pair col sx+x <= 157
        // (pair (157,158) valid; col-159 pair never read).
        const float2* s1 = splane2 + sy1 * W_ + sx1 + x;
        const float2* s2 = splane2 + sy2 * W_ + sx2 + x;
        float* op = out + (size_t)nmk * PLANE_ + y0 * OW_ + x;

        // prologue: row-0 horizontal lerp (one LDS.64 per sample)
        float2 a = s1[0];
        float2 b = s2[0];
        float prev1 = g1x * a.x + f1x * a.y;
        float prev2 = g2x * b.x + f2x * b.y;

        #pragma unroll
        for (int r = 1; r <= HTILE_; r++) {
            const float2 av = s1[r * W_];
            const float2 bv = s2[r * W_];
            const float cur1 = g1x * av.x + f1x * av.y;
            const float cur2 = g2x * bv.x + f2x * bv.y;

            float temp = g1y * prev1;
            temp = fmaf(f1y,  cur1,  temp);
            temp = fmaf(ng2y, prev2, temp);
            temp = fmaf(nf2y, cur2,  temp);
            prev1 = cur1;
            prev2 = cur2;

            if (fabsf(temp) < 1e-5f) temp = 0.0f;
            op[(r - 1) * OW_] = __saturatef(fmaf(temp, inv, c));
        }
    }
}

extern "C" void kernel_launch(void* const* d_in, const int* in_sizes, int n_in,
                              void* d_out, int out_size)
{
    const float* T        = (const float*)d_in[0];
    const float* dx1      = (const float*)d_in[1];
    const float* dx2      = (const float*)d_in[2];
    const float* dy1      = (const float*)d_in[3];
    const float* dy2      = (const float*)d_in[4];
    const float* th       = (const float*)d_in[5];
    const float* amb      = (const float*)d_in[6];
    const int*   channels = (const int*)  d_in[7];
    float* out = (float*)d_out;

    fern_bits_kernel<<<NBLOCKS_, 256>>>(
        T, dx1, dx2, dy1, dy2, th, amb, channels, out);
}

// round 16
// speedup vs baseline: 1.1209x; 1.1209x over previous
#include <cuda_runtime.h>

// Problem constants (fixed by the reference module)
#define N_  16
#define D_  3
#define H_  160
#define W_  160
#define M_  8
#define K_  10
#define P_  15
#define PM_ 7               // (P-1)/2
#define OH_ (H_ - P_ + 1)   // 146
#define OW_ (W_ - P_ + 1)   // 146
#define MK_ (M_ * K_)       // 80
#define PLANE_ (OH_ * OW_)  // 21316

// Block = (plane=(n,k), rg). All 8 m for a given k sample the same
// (n, channels[k]) plane: stage 24 input rows in smem once; warp m computes
// its band. 5 column bands of 32 (last clamped to x0=114); overlapped
// regions write identical values (deterministic).
//
// WAVE-EXACT GRID: concurrency = 148 SMs x 8 blocks = 1184. Grid is set to
// exactly 2 waves: 2368 blocks. Planes 0..127 use 15 row groups of HTILE=10
// (last clamped); planes 128..159 use 14 row groups of HTILE=11 (last
// clamped). 128*15 + 32*14 = 2368.
#define SROWS_ 24                      // covers sy(<=12) + HT(<=11) = 23
#define SMEM_FLOATS_ (SROWS_ * W_)     // 3840 floats = 15360 B
#define SPLIT_   (128 * 15)            // 1920 blocks with HT=10
#define NBLOCKS_ (SPLIT_ + 32 * 14)    // 2368 = 148*8*2

template<int HT>
__device__ __forceinline__ void band_sweep(
    const float* __restrict__ splane, float* __restrict__ outbase,
    int lane, int y0,
    int sx1, int sy1, int sx2, int sy2,
    float f1x, float g1x, float f2x, float g2x,
    float f1y, float g1y, float ng2y, float nf2y,
    float inv, float c)
{
    #pragma unroll 1
    for (int cb = 0; cb < 5; cb++) {
        const int x0 = min(cb * 32, OW_ - 32);   // 0,32,64,96,114
        const int x  = x0 + lane;

        // smem tap bases: rows used <= sy+HT <= 23 < 24;
        // cols: sx<=12, x<=145 -> 158 < 160.
        const float* s1 = splane + sy1 * W_ + sx1 + x;
        const float* s2 = splane + sy2 * W_ + sx2 + x;
        float* op = outbase + y0 * OW_ + x;

        // prologue: horizontal lerp of band input row 0
        float prev1 = g1x * s1[0] + f1x * s1[1];
        float prev2 = g2x * s2[0] + f2x * s2[1];

        #pragma unroll
        for (int r = 1; r <= HT; r++) {
            const float a0 = s1[r * W_], a1 = s1[r * W_ + 1];
            const float b0 = s2[r * W_], b1 = s2[r * W_ + 1];
            const float cur1 = g1x * a0 + f1x * a1;
            const float cur2 = g2x * b0 + f2x * b1;

            float temp = g1y * prev1;
            temp = fmaf(f1y,  cur1,  temp);
            temp = fmaf(ng2y, prev2, temp);
            temp = fmaf(nf2y, cur2,  temp);
            prev1 = cur1;
            prev2 = cur2;

            if (fabsf(temp) < 1e-5f) temp = 0.0f;
            op[(r - 1) * OW_] = __saturatef(fmaf(temp, inv, c));
        }
    }
}

__global__ __launch_bounds__(256, 8)   // 32 regs, 8 blocks/SM
void fern_bits_kernel(
    const float* __restrict__ T,
    const float* __restrict__ dx1, const float* __restrict__ dx2,
    const float* __restrict__ dy1, const float* __restrict__ dy2,
    const float* __restrict__ th,  const float* __restrict__ amb,
    const int*   __restrict__ channels,
    float* __restrict__ out)
{
    __shared__ float splane[SMEM_FLOATS_];

    // ---- block decode: mixed row-group schedule ----
    const int bid = blockIdx.x;
    int p, rg, ht, y0;
    if (bid < SPLIT_) {                 // planes 0..127: 15 groups of HT=10
        p  = bid / 15;
        rg = bid - p * 15;
        ht = 10;
        y0 = min(rg * 10, OH_ - 10);    // 0..140 -> clamp 136
    } else {                            // planes 128..159: 14 groups of HT=11
        const int b2 = bid - SPLIT_;
        p  = 128 + b2 / 14;
        rg = b2 - (p - 128) * 14;
        ht = 11;
        y0 = min(rg * 11, OH_ - 11);    // 0..143 -> clamp 135
    }
    const int k  = p % K_;
    const int n  = p / K_;
    const int ch = channels[k];
    // staged rows [y0, y0+23]; max = 136+23 = 159 < 160. OK.

    // ---- cooperative staging: linear float4 copy (960 float4s) ----
    const float* __restrict__ img = T + ((size_t)(n * D_ + ch)) * (H_ * W_);
    {
        const float4* __restrict__ g4 = (const float4*)(img + y0 * W_);
        float4* s4 = (float4*)splane;
        for (int i = threadIdx.x; i < SMEM_FLOATS_ / 4; i += 256)
            s4[i] = g4[i];
    }
    __syncthreads();

    // ---- per-warp: one m value ----
    const int m    = threadIdx.x >> 5;
    const int lane = threadIdx.x & 31;
    const int mk   = m * K_ + k;
    const int nmk  = n * MK_ + mk;

    // per-(m,k) parameters (uniform per warp, broadcast loads)
    const float a1x = dx1[mk], a2x = dx2[mk];
    const float a1y = dy1[mk], a2y = dy2[mk];
    const float fl1x = floorf(a1x), fl2x = floorf(a2x);
    const float fl1y = floorf(a1y), fl2y = floorf(a2y);
    const float f1x = a1x - fl1x, f2x = a2x - fl2x;
    const float f1y = a1y - fl1y, f2y = a2y - fl2y;
    const float g1x = 1.0f - f1x, g2x = 1.0f - f2x;
    const float g1y  = 1.0f - f1y;
    const float ng2y = -(1.0f - f2y), nf2y = -f2y;
    const int sx1 = PM_ + (int)fl1x, sx2 = PM_ + (int)fl2x;
    const int sy1 = PM_ + (int)fl1y, sy2 = PM_ + (int)fl2y;

    const float thv = th[mk];
    const float pos = amb[(m * 2 + 0) * K_ + k];
    const float neg = amb[(m * 2 + 1) * K_ + k];
    const float inv = 1.0f / (pos - neg + 1e-29f);
    const float c   = -(thv + neg) * inv;   // v = sat(temp*inv + c)

    float* outbase = out + (size_t)nmk * PLANE_;

    if (ht == 10)
        band_sweep<10>(splane, outbase, lane, y0,
                       sx1, sy1, sx2, sy2,
                       f1x, g1x, f2x, g2x, f1y, g1y, ng2y, nf2y, inv, c);
    else
        band_sweep<11>(splane, outbase, lane, y0,
                       sx1, sy1, sx2, sy2,
                       f1x, g1x, f2x, g2x, f1y, g1y, ng2y, nf2y, inv, c);
}

extern "C" void kernel_launch(void* const* d_in, const int* in_sizes, int n_in,
                              void* d_out, int out_size)
{
    const float* T        = (const float*)d_in[0];
    const float* dx1      = (const float*)d_in[1];
    const float* dx2      = (const float*)d_in[2];
    const float* dy1      = (const float*)d_in[3];
    const float* dy2      = (const float*)d_in[4];
    const float* th       = (const float*)d_in[5];
    const float* amb      = (const float*)d_in[6];
    const int*   channels = (const int*)  d_in[7];
    float* out = (float*)d_out;

    fern_bits_kernel<<<NBLOCKS_, 256>>>(
        T, dx1, dx2, dy1, dy2, th, amb, channels, out);
}